// round 4
// baseline (speedup 1.0000x reference)
#include <cuda_runtime.h>
#include <cuda_fp16.h>

#define NA 4096
#define H  64
#define OD 48
#define NSEG 48
#define PC (NSEG * OD)   /* 2304 */
#define PROWB 4608u      /* bytes per fp16 P row */

// Scratch (device globals: allocation-free rule). +64 pad halfs for the
// sentinel (s=48) read of the last row.
__device__ __half g_P[(size_t)NA * PC + 64];  // 18.9 MB, L2-resident
__device__ float  g_Wt[H * PC];               // 589 KB reshaped weights

// ---------------------------------------------------------------------------
// Wt[k][s*48+o] = fc_w[o, s*64+k];  also zero the g_P sentinel pad.
// ---------------------------------------------------------------------------
__global__ void k_reshape(const float* __restrict__ fw) {
    int idx = blockIdx.x * blockDim.x + threadIdx.x;
    if (idx < 64) g_P[(size_t)NA * PC + idx] = __float2half(0.f);
    if (idx >= H * PC) return;
    int k = idx / PC, c = idx - k * PC;
    int s = c / OD, o = c - s * OD;
    g_Wt[idx] = fw[o * (NSEG * H) + s * H + k];
}

// ---------------------------------------------------------------------------
// P[j][c] = sum_k hidden[j][k] * Wt[k][c]  (8 j-rows/block; fp32 acc, fp16 out)
// ---------------------------------------------------------------------------
#define GR 8
__global__ __launch_bounds__(256) void k_gemmP(const float* __restrict__ hidden) {
    __shared__ float sh[GR][H];
    int t = threadIdx.x;
    int jb = blockIdx.x * GR;
    for (int idx = t; idx < GR * H; idx += 256)
        sh[idx >> 6][idx & 63] = hidden[jb * H + idx];
    __syncthreads();

    float acc[GR][9];
#pragma unroll
    for (int j = 0; j < GR; j++)
#pragma unroll
        for (int u = 0; u < 9; u++) acc[j][u] = 0.f;

    for (int k = 0; k < H; k++) {
        float w[9];
#pragma unroll
        for (int u = 0; u < 9; u++) w[u] = g_Wt[k * PC + u * 256 + t];
#pragma unroll
        for (int j = 0; j < GR; j++) {
            float hv = sh[j][k];
#pragma unroll
            for (int u = 0; u < 9; u++) acc[j][u] = fmaf(hv, w[u], acc[j][u]);
        }
    }
#pragma unroll
    for (int j = 0; j < GR; j++)
#pragma unroll
        for (int u = 0; u < 9; u++)
            g_P[(size_t)(jb + j) * PC + u * 256 + t] = __float2half_rn(acc[j][u]);
}

// ---------------------------------------------------------------------------
// seg(i,j): MUFU-free (ring via r^2 thresholds, wedge via octant compares,
// exactly replicating trunc(atan2*4/pi + 3) mod 8). 48 = invalid sentinel.
// ---------------------------------------------------------------------------
__device__ __forceinline__ int seg_of(float xi, float yi, float xj, float yj) {
    float dx = xj - xi, dy = yj - yi;
    float r2 = fmaf(dx, dx, dy * dy);
    if (r2 < 0.25f)          return NSEG;
    if (r2 >= 36.75834735f)  return NSEG;
    int ring = (r2 >= 0.574349177f) + (r2 >= 1.319507911f) + (r2 >= 3.031433132f)
             + (r2 >= 6.964404507f) + (r2 >= 16.0f);
    int w;
    if (dy > 0.f) {
        if (dx > 0.f)      w = (dy <  dx) ? 3 : 4;
        else if (dx < 0.f) w = (dy > -dx) ? 5 : 6;
        else               w = 5;
    } else if (dy < 0.f) {
        if (dx > 0.f)      w = (-dy <= dx) ? 2 : 1;
        else if (dx < 0.f) w = 0;
        else               w = 1;
    } else {
        w = (dx >= 0.f) ? 3 : 7;
    }
    return ring * 8 + w;
}

// ---------------------------------------------------------------------------
// Main: one warp per agent i, 4 warps/block.
// Sweep 1: seg -> smem u8 + lane-private u32 histogram (conflict-free).
// Sweep 2: branch-free pipelined gather-FMA over fp16 P with sentinel weight 0.
// ---------------------------------------------------------------------------
__global__ __launch_bounds__(128) void k_main(const float2* __restrict__ yp,
                                              const float* __restrict__ fb,
                                              float* __restrict__ out) {
    __shared__ unsigned int  hist[4][48 * 33];
    __shared__ unsigned char segs[4][NA];
    __shared__ float         wtab[4][64];
    int wp = threadIdx.x >> 5, lane = threadIdx.x & 31;
    int i = blockIdx.x * 4 + wp;
    float2 pi = yp[i];

    for (int idx = lane; idx < 48 * 33; idx += 32) hist[wp][idx] = 0;
    __syncwarp();

    // ---- sweep 1: segment ids + counts ----
    for (int base = 0; base < NA; base += 32) {
        float2 pj = yp[base + lane];
        int s = seg_of(pi.x, pi.y, pj.x, pj.y);
        segs[wp][base + lane] = (unsigned char)s;
        if (s < NSEG) hist[wp][s * 33 + lane]++;
    }
    __syncwarp();
    for (int s = lane; s < 64; s += 32) {
        float w = 0.f;
        if (s < NSEG) {
            unsigned c = 0;
#pragma unroll
            for (int k = 0; k < 32; k++) c += hist[wp][s * 33 + k];
            w = (c > 0) ? (1.0f / (float)c) : 0.0f;
        }
        wtab[wp][s] = w;   // wtab[48] = 0 -> sentinel kills invalid pairs
    }
    __syncwarp();

    // ---- sweep 2: straight-line gather-FMA (no branches, full MLP) ----
    int l24 = (lane < 24) ? lane : lane - 24;   // mirror: same 128B lines
    const unsigned char* Pb = (const unsigned char*)g_P + (unsigned)l24 * 4u;
    float ax = 0.f, ay = 0.f, bx2 = 0.f, by2 = 0.f;
    for (int j0 = 0; j0 < NA; j0 += 8) {
#pragma unroll
        for (int u = 0; u < 8; u++) {
            int j = j0 + u;
            int s = segs[wp][j];                       // LDS.U8 broadcast
            float w = wtab[wp][s];                     // LDS broadcast
            const __half2* p =
                (const __half2*)(Pb + (unsigned)j * PROWB + (unsigned)s * 96u);
            float2 v = __half22float2(*p);             // coalesced 96B gather
            if (u & 1) { bx2 = fmaf(w, v.x, bx2); by2 = fmaf(w, v.y, by2); }
            else       { ax  = fmaf(w, v.x, ax);  ay  = fmaf(w, v.y, ay);  }
        }
    }
    ax += bx2; ay += by2;

    if (lane < 24) {
        float r0 = ax + fb[2 * lane];
        float r1 = ay + fb[2 * lane + 1];
        float2 res = make_float2(fmaxf(r0, 0.f), fmaxf(r1, 0.f));
        *(float2*)(out + i * OD + 2 * lane) = res;
    }
}

// ---------------------------------------------------------------------------
extern "C" void kernel_launch(void* const* d_in, const int* in_sizes, int n_in,
                              void* d_out, int out_size) {
    const float* ypred  = (const float*)d_in[0];
    const float* hidden = (const float*)d_in[1];
    const float* fc_w   = (const float*)d_in[2];
    const float* fc_b   = (const float*)d_in[3];
    float* out = (float*)d_out;

    k_reshape<<<(H * PC + 255) / 256, 256>>>(fc_w);
    k_gemmP<<<NA / GR, 256>>>(hidden);
    k_main<<<NA / 4, 128>>>((const float2*)ypred, fc_b, out);
}

// round 6
// speedup vs baseline: 1.3395x; 1.3395x over previous
#include <cuda_runtime.h>
#include <cuda_fp16.h>

#define NA 4096
#define H  64
#define OD 48
#define NSEG 48
#define PC (NSEG * OD)   /* 2304 */
#define PROWB 4608u      /* bytes per fp16 P row */

// Scratch (device globals: allocation-free rule). +64 pad halfs so the
// sentinel (s=48) gather on the last row stays in-bounds.
__device__ __half g_P[(size_t)NA * PC + 64];  // 18.9 MB, L2-resident
__device__ float  g_Wt[H * PC];               // 589 KB reshaped weights

// ---------------------------------------------------------------------------
// Wt[k][s*48+o] = fc_w[o, s*64+k];  also zero the g_P sentinel pad.
// ---------------------------------------------------------------------------
__global__ void k_reshape(const float* __restrict__ fw) {
    int idx = blockIdx.x * blockDim.x + threadIdx.x;
    if (idx < 64) g_P[(size_t)NA * PC + idx] = __float2half(0.f);
    if (idx >= H * PC) return;
    int k = idx / PC, c = idx - k * PC;
    int s = c / OD, o = c - s * OD;
    g_Wt[idx] = fw[o * (NSEG * H) + s * H + k];
}

// ---------------------------------------------------------------------------
// P[j][c] = sum_k hidden[j][k] * Wt[k][c]  (8 j-rows/block; fp32 acc, fp16 out)
// ---------------------------------------------------------------------------
#define GR 8
__global__ __launch_bounds__(256) void k_gemmP(const float* __restrict__ hidden) {
    __shared__ float sh[GR][H];
    int t = threadIdx.x;
    int jb = blockIdx.x * GR;
    for (int idx = t; idx < GR * H; idx += 256)
        sh[idx >> 6][idx & 63] = hidden[jb * H + idx];
    __syncthreads();

    float acc[GR][9];
#pragma unroll
    for (int j = 0; j < GR; j++)
#pragma unroll
        for (int u = 0; u < 9; u++) acc[j][u] = 0.f;

    for (int k = 0; k < H; k++) {
        float w[9];
#pragma unroll
        for (int u = 0; u < 9; u++) w[u] = g_Wt[k * PC + u * 256 + t];
#pragma unroll
        for (int j = 0; j < GR; j++) {
            float hv = sh[j][k];
#pragma unroll
            for (int u = 0; u < 9; u++) acc[j][u] = fmaf(hv, w[u], acc[j][u]);
        }
    }
#pragma unroll
    for (int j = 0; j < GR; j++)
#pragma unroll
        for (int u = 0; u < 9; u++)
            g_P[(size_t)(jb + j) * PC + u * 256 + t] = __float2half_rn(acc[j][u]);
}

// ---------------------------------------------------------------------------
// seg(i,j): MUFU-free (ring via r^2 thresholds, wedge via octant compares,
// exactly replicating trunc(atan2*4/pi + 3) mod 8). 48 = invalid sentinel.
// ---------------------------------------------------------------------------
__device__ __forceinline__ int seg_of(float xi, float yi, float xj, float yj) {
    float dx = xj - xi, dy = yj - yi;
    float r2 = fmaf(dx, dx, dy * dy);
    if (r2 < 0.25f)          return NSEG;
    if (r2 >= 36.75834735f)  return NSEG;
    int ring = (r2 >= 0.574349177f) + (r2 >= 1.319507911f) + (r2 >= 3.031433132f)
             + (r2 >= 6.964404507f) + (r2 >= 16.0f);
    int w;
    if (dy > 0.f) {
        if (dx > 0.f)      w = (dy <  dx) ? 3 : 4;
        else if (dx < 0.f) w = (dy > -dx) ? 5 : 6;
        else               w = 5;
    } else if (dy < 0.f) {
        if (dx > 0.f)      w = (-dy <= dx) ? 2 : 1;
        else if (dx < 0.f) w = 0;
        else               w = 1;
    } else {
        w = (dx >= 0.f) ? 3 : 7;
    }
    return ring * 8 + w;
}

// ---------------------------------------------------------------------------
// Main: one warp per agent i, 8 warps/block, 27KB smem -> 64 warps/SM.
// Sweep 1: counts via lane-private u16 histograms (no atomics, no segs array).
// Sweep 2: seg recomputed thread-parallel per 32-chunk, SHFL-broadcast,
//          branch-free sentinel gather (wtab[48]=0) -> full LDG batching.
// ---------------------------------------------------------------------------
__global__ __launch_bounds__(256) void k_main(const float2* __restrict__ yp,
                                              const float* __restrict__ fb,
                                              float* __restrict__ out) {
    __shared__ unsigned short hist[8][48 * 33];
    __shared__ float          wtab[8][64];
    int wp = threadIdx.x >> 5, lane = threadIdx.x & 31;
    int i = blockIdx.x * 8 + wp;
    float2 pi = yp[i];

    for (int idx = lane; idx < 48 * 33; idx += 32) hist[wp][idx] = 0;
    __syncwarp();

    // ---- sweep 1: per-segment counts ----
    for (int base = 0; base < NA; base += 32) {
        float2 pj = yp[base + lane];
        int s = seg_of(pi.x, pi.y, pj.x, pj.y);
        if (s < NSEG) hist[wp][s * 33 + lane]++;   // max per-lane count = 128
    }
    __syncwarp();
    for (int s = lane; s < 64; s += 32) {
        float w = 0.f;
        if (s < NSEG) {
            unsigned c = 0;
#pragma unroll
            for (int k = 0; k < 32; k++) c += hist[wp][s * 33 + k];
            w = (c > 0) ? (1.0f / (float)c) : 0.0f;
        }
        wtab[wp][s] = w;   // wtab[48] = 0 -> sentinel kills invalid pairs
    }
    __syncwarp();

    // ---- sweep 2: branch-free gather-FMA over fp16 P ----
    int l24 = (lane < 24) ? lane : lane - 24;   // mirror lanes: same sectors
    const unsigned char* Pb = (const unsigned char*)g_P + (unsigned)l24 * 4u;
    float ax = 0.f, ay = 0.f, bx2 = 0.f, by2 = 0.f;
    for (int base = 0; base < NA; base += 32) {
        float2 pj = yp[base + lane];
        int s = seg_of(pi.x, pi.y, pj.x, pj.y);   // thread-parallel, 1 per lane
        const unsigned char* rowb = Pb + (size_t)base * PROWB;
#pragma unroll
        for (int k = 0; k < 32; k++) {
            int sk = __shfl_sync(0xffffffffu, s, k);
            float w = wtab[wp][sk];                          // LDS broadcast
            const __half2* p =
                (const __half2*)(rowb + (unsigned)k * PROWB + (unsigned)sk * 96u);
            float2 v = __half22float2(*p);                   // coalesced gather
            if (k & 1) { bx2 = fmaf(w, v.x, bx2); by2 = fmaf(w, v.y, by2); }
            else       { ax  = fmaf(w, v.x, ax);  ay  = fmaf(w, v.y, ay);  }
        }
    }
    ax += bx2; ay += by2;

    if (lane < 24) {
        float r0 = ax + fb[2 * lane];
        float r1 = ay + fb[2 * lane + 1];
        float2 res = make_float2(fmaxf(r0, 0.f), fmaxf(r1, 0.f));
        *(float2*)(out + i * OD + 2 * lane) = res;
    }
}

// ---------------------------------------------------------------------------
extern "C" void kernel_launch(void* const* d_in, const int* in_sizes, int n_in,
                              void* d_out, int out_size) {
    const float* ypred  = (const float*)d_in[0];
    const float* hidden = (const float*)d_in[1];
    const float* fc_w   = (const float*)d_in[2];
    const float* fc_b   = (const float*)d_in[3];
    float* out = (float*)d_out;

    k_reshape<<<(H * PC + 255) / 256, 256>>>(fc_w);
    k_gemmP<<<NA / GR, 256>>>(hidden);
    k_main<<<NA / 8, 256>>>((const float2*)ypred, fc_b, out);
}

// round 7
// speedup vs baseline: 1.6771x; 1.2521x over previous
#include <cuda_runtime.h>
#include <cuda_fp16.h>

#define NA 4096
#define H  64
#define OD 48
#define NSEG 48
#define PC (NSEG * OD)   /* 2304 */
#define PROWB 4608u      /* bytes per fp16 P row */

// Scratch (device globals: allocation-free rule). +64 pad halfs so the
// sentinel (s=48) gather on the last row stays in-bounds.
__device__ __half        g_P[(size_t)NA * PC + 64];  // 18.9 MB, L2-resident
__device__ float         g_Wt[H * PC];               // 589 KB reshaped weights
__device__ unsigned char g_seg[(size_t)NA * NA];     // 16.7 MB seg ids
__device__ float         g_invc[NA * 64];            // 1/count per (i,s), 0-padded

// ---------------------------------------------------------------------------
// Wt[k][s*48+o] = fc_w[o, s*64+k];  also zero the g_P sentinel pad.
// ---------------------------------------------------------------------------
__global__ void k_reshape(const float* __restrict__ fw) {
    int idx = blockIdx.x * blockDim.x + threadIdx.x;
    if (idx < 64) g_P[(size_t)NA * PC + idx] = __float2half(0.f);
    if (idx >= H * PC) return;
    int k = idx / PC, c = idx - k * PC;
    int s = c / OD, o = c - s * OD;
    g_Wt[idx] = fw[o * (NSEG * H) + s * H + k];
}

// ---------------------------------------------------------------------------
// P[j][c] = sum_k hidden[j][k] * Wt[k][c]  (8 j-rows/block; fp32 acc, fp16 out)
// ---------------------------------------------------------------------------
#define GR 8
__global__ __launch_bounds__(256) void k_gemmP(const float* __restrict__ hidden) {
    __shared__ float sh[GR][H];
    int t = threadIdx.x;
    int jb = blockIdx.x * GR;
    for (int idx = t; idx < GR * H; idx += 256)
        sh[idx >> 6][idx & 63] = hidden[jb * H + idx];
    __syncthreads();

    float acc[GR][9];
#pragma unroll
    for (int j = 0; j < GR; j++)
#pragma unroll
        for (int u = 0; u < 9; u++) acc[j][u] = 0.f;

    for (int k = 0; k < H; k++) {
        float w[9];
#pragma unroll
        for (int u = 0; u < 9; u++) w[u] = g_Wt[k * PC + u * 256 + t];
#pragma unroll
        for (int j = 0; j < GR; j++) {
            float hv = sh[j][k];
#pragma unroll
            for (int u = 0; u < 9; u++) acc[j][u] = fmaf(hv, w[u], acc[j][u]);
        }
    }
#pragma unroll
    for (int j = 0; j < GR; j++)
#pragma unroll
        for (int u = 0; u < 9; u++)
            g_P[(size_t)(jb + j) * PC + u * 256 + t] = __float2half_rn(acc[j][u]);
}

// ---------------------------------------------------------------------------
// seg(i,j): MUFU-free (ring via r^2 thresholds, wedge via octant compares,
// exactly replicating trunc(atan2*4/pi + 3) mod 8). 48 = invalid sentinel.
// ---------------------------------------------------------------------------
__device__ __forceinline__ int seg_of(float xi, float yi, float xj, float yj) {
    float dx = xj - xi, dy = yj - yi;
    float r2 = fmaf(dx, dx, dy * dy);
    if (r2 < 0.25f)          return NSEG;
    if (r2 >= 36.75834735f)  return NSEG;
    int ring = (r2 >= 0.574349177f) + (r2 >= 1.319507911f) + (r2 >= 3.031433132f)
             + (r2 >= 6.964404507f) + (r2 >= 16.0f);
    int w;
    if (dy > 0.f) {
        if (dx > 0.f)      w = (dy <  dx) ? 3 : 4;
        else if (dx < 0.f) w = (dy > -dx) ? 5 : 6;
        else               w = 5;
    } else if (dy < 0.f) {
        if (dx > 0.f)      w = (-dy <= dx) ? 2 : 1;
        else if (dx < 0.f) w = 0;
        else               w = 1;
    } else {
        w = (dx >= 0.f) ? 3 : 7;
    }
    return ring * 8 + w;
}

// ---------------------------------------------------------------------------
// k_seg: warp per i. Computes g_seg[i][j] (u8) and g_invc[i][s] (1/count).
// Lane-parallel seg_of; lane-private u16 histograms (no atomics).
// ---------------------------------------------------------------------------
__global__ __launch_bounds__(256) void k_seg(const float2* __restrict__ yp) {
    __shared__ unsigned short hist[8][48 * 33];
    int wp = threadIdx.x >> 5, lane = threadIdx.x & 31;
    int i = blockIdx.x * 8 + wp;
    float2 pi = yp[i];

    for (int idx = lane; idx < 48 * 33; idx += 32) hist[wp][idx] = 0;
    __syncwarp();

    unsigned char* segrow = g_seg + (size_t)i * NA;
    for (int base = 0; base < NA; base += 32) {
        float2 pj = yp[base + lane];
        int s = seg_of(pi.x, pi.y, pj.x, pj.y);
        segrow[base + lane] = (unsigned char)s;
        if (s < NSEG) hist[wp][s * 33 + lane]++;   // max per-lane count = 128
    }
    __syncwarp();
    for (int s = lane; s < 64; s += 32) {
        float w = 0.f;
        if (s < NSEG) {
            unsigned c = 0;
#pragma unroll
            for (int k = 0; k < 32; k++) c += hist[wp][s * 33 + k];
            w = (c > 0) ? (1.0f / (float)c) : 0.0f;
        }
        g_invc[i * 64 + s] = w;   // s=48..63 -> 0 (sentinel weight)
    }
}

// ---------------------------------------------------------------------------
// k_main: warp per i, 8 warps/block, 10KB smem -> full occupancy.
// Pair-split gather: lanes 0-11 own pair 2t (4 outs each), lanes 12-23 own
// pair 2t+1, lanes 24-31 mirror lanes 0-7 (same sectors, unpredicated LDG).
// Segs staged in smem per 1024-j chunk; wtab[48]=0 sentinel kills invalid.
// ---------------------------------------------------------------------------
__global__ __launch_bounds__(256) void k_main(const float* __restrict__ fb,
                                              float* __restrict__ out) {
    __shared__ float         wtab[8][64];
    __shared__ unsigned char segbuf[8][1024];
    int wp = threadIdx.x >> 5, lane = threadIdx.x & 31;
    int i = blockIdx.x * 8 + wp;

    for (int s = lane; s < 64; s += 32) wtab[wp][s] = g_invc[i * 64 + s];
    __syncwarp();

    // lane roles
    int lo  = (lane < 12) ? lane : ((lane < 24) ? lane - 12 : lane - 24);
    int odd = (lane >= 12 && lane < 24) ? 1 : 0;
    const unsigned char* Pb = (const unsigned char*)g_P + (unsigned)lo * 8u;

    float a0 = 0.f, a1 = 0.f, a2 = 0.f, a3 = 0.f;
    const unsigned char* segrow = g_seg + (size_t)i * NA;

    for (int c0 = 0; c0 < NA; c0 += 1024) {
        // stage 1024 seg bytes (warp-private)
        const uint4* src = (const uint4*)(segrow + c0);
        uint4* dst = (uint4*)segbuf[wp];
        dst[lane]      = src[lane];
        dst[lane + 32] = src[lane + 32];
        __syncwarp();

        const unsigned char* rowb = Pb + (size_t)c0 * PROWB;
#pragma unroll 8
        for (int t = 0; t < 512; t++) {
            int p = 2 * t + odd;
            int s = segbuf[wp][p];                  // LDS.U8 (2 addrs max)
            float w = wtab[wp][s];                  // LDS (2 addrs max)
            uint2 v = *(const uint2*)(rowb + (unsigned)p * PROWB + (unsigned)s * 96u);
            float2 f0 = __half22float2(*(const __half2*)&v.x);
            float2 f1 = __half22float2(*(const __half2*)&v.y);
            a0 = fmaf(w, f0.x, a0); a1 = fmaf(w, f0.y, a1);
            a2 = fmaf(w, f1.x, a2); a3 = fmaf(w, f1.y, a3);
        }
        __syncwarp();
    }

    // combine even/odd accumulators: lane l (<12) += lane l+12
    a0 += __shfl_down_sync(0xffffffffu, a0, 12);
    a1 += __shfl_down_sync(0xffffffffu, a1, 12);
    a2 += __shfl_down_sync(0xffffffffu, a2, 12);
    a3 += __shfl_down_sync(0xffffffffu, a3, 12);

    if (lane < 12) {
        const float4 b = ((const float4*)fb)[lane];
        float4 r;
        r.x = fmaxf(a0 + b.x, 0.f);
        r.y = fmaxf(a1 + b.y, 0.f);
        r.z = fmaxf(a2 + b.z, 0.f);
        r.w = fmaxf(a3 + b.w, 0.f);
        *(float4*)(out + i * OD + 4 * lane) = r;
    }
}

// ---------------------------------------------------------------------------
extern "C" void kernel_launch(void* const* d_in, const int* in_sizes, int n_in,
                              void* d_out, int out_size) {
    const float* ypred  = (const float*)d_in[0];
    const float* hidden = (const float*)d_in[1];
    const float* fc_w   = (const float*)d_in[2];
    const float* fc_b   = (const float*)d_in[3];
    float* out = (float*)d_out;

    k_reshape<<<(H * PC + 255) / 256, 256>>>(fc_w);
    k_gemmP<<<NA / GR, 256>>>(hidden);
    k_seg<<<NA / 8, 256>>>((const float2*)ypred);
    k_main<<<NA / 8, 256>>>(fc_b, out);
}